// round 2
// baseline (speedup 1.0000x reference)
#include <cuda_runtime.h>

#define NXg 256
#define NYg 256
#define NCELL (NXg*NYg)
#define TSTEPS 256
#define NSIG 2
#define TR 32            // tile rows (x / axis-2)
#define TC 16            // tile cols (y / axis-3)
#define ER (TR+8)        // extended rows = 40
#define EC (TC+8)        // extended cols = 24
#define EP 25            // padded SMEM pitch
#define NLOC (ER*EC)     // 960 local cells
#define NTH 256
#define CPT ((NLOC + NTH - 1)/NTH)   // 4 cells per thread

// Ping-pong magnetization state: [buf][signal][component*NCELL + x*NY + y]
__device__ float g_m[2][NSIG][3*NCELL];

__global__ void mm_init_kernel() {
    int i = blockIdx.x*blockDim.x + threadIdx.x;
    if (i < NSIG*NCELL) {
        int s = i >> 16;
        int idx = i & (NCELL-1);
        g_m[0][s][0*NCELL + idx] = 0.0f;   // mx
        g_m[0][s][1*NCELL + idx] = 1.0f;   // my  (relaxed state == m0 exactly, see analysis)
        g_m[0][s][2*NCELL + idx] = 0.0f;   // mz
    }
}

__global__ __launch_bounds__(NTH) void mm_step_kernel(
    int src_buf, int t,
    const float* __restrict__ sig,        // (NSIG, TSTEPS, 3)
    const float* __restrict__ Bext,       // (1,3,NX,NY)
    const float* __restrict__ Msat_p,     // scalar
    const int*   __restrict__ src_pos,    // (3,2)
    const int*   __restrict__ probe_pos,  // (5,2)
    float*       __restrict__ out)        // (NSIG, TSTEPS, 5)
{
    __shared__ float stg[2][3][ER*EP];

    const int s   = blockIdx.z;
    const int ti0 = blockIdx.y * TR;
    const int tj0 = blockIdx.x * TC;
    const float* __restrict__ m_in  = g_m[src_buf][s];
    float* __restrict__       m_out = g_m[src_buf ^ 1][s];

    const float Msat  = Msat_p[0];
    const float cexch = 7.0e-12f / ((Msat * 5e-8f) * 5e-8f);  // 2*A/(Msat*dx^2)
    const float cdem  = 1.2566371e-06f * Msat;                // mu0*Msat (z-only demag)
    const float alpha = 0.01f;
    const float pref  = -1.0f / (1.0f + alpha*alpha);
    const float csot  = 1.0e-4f;
    const float hh    = 0.87975f;                 // GAMMA_LL*DT
    const float ch    = 0.439875f;                // 0.5*h
    const float h6    = (float)(0.87975/6.0);

    const int tid = threadIdx.x;

    // per-thread source / signal cache
    int   sp[6];
    float sv[3];
    #pragma unroll
    for (int k = 0; k < 3; k++) {
        sp[2*k]   = src_pos[2*k];
        sp[2*k+1] = src_pos[2*k+1];
        sv[k]     = sig[(s*TSTEPS + t)*3 + k];
    }

    // per-cell precomputed state
    int   cidx[CPT], nU[CPT], nD[CPT], nL[CPT], nR[CPT];
    int   li_[CPT], lj_[CPT], gidx[CPT];
    bool  ingrid[CPT];
    float Bx[CPT], By[CPT], Bz[CPT];
    float mrx[CPT], mry[CPT], mrz[CPT];
    float ax[CPT], ay[CPT], az[CPT];

    #pragma unroll
    for (int q = 0; q < CPT; q++) {
        int idx = tid + q*NTH;
        bool valid = idx < NLOC;
        int li = valid ? idx / EC : 0;
        int lj = valid ? idx % EC : 0;
        int gi = ti0 - 4 + li;
        int gj = tj0 - 4 + lj;
        li_[q] = li; lj_[q] = lj;
        bool ing = valid && gi >= 0 && gi < NXg && gj >= 0 && gj < NYg;
        ingrid[q] = ing;
        cidx[q] = li*EP + lj;
        // neighbor coordinates with global clamp (edge padding), mapped to local
        int giu = (gi-1 < 0)      ? 0       : gi-1;
        int gid = (gi+1 > NXg-1)  ? NXg-1   : gi+1;
        int gjl = (gj-1 < 0)      ? 0       : gj-1;
        int gjr = (gj+1 > NYg-1)  ? NYg-1   : gj+1;
        nU[q] = (giu - (ti0-4))*EP + lj;
        nD[q] = (gid - (ti0-4))*EP + lj;
        nL[q] = li*EP + (gjl - (tj0-4));
        nR[q] = li*EP + (gjr - (tj0-4));
        int g = gi*NYg + gj;
        gidx[q] = g;
        ax[q] = ay[q] = az[q] = 0.0f;
        if (ing) {
            mrx[q] = m_in[g];
            mry[q] = m_in[NCELL + g];
            mrz[q] = m_in[2*NCELL + g];
            float bx = Bext[g];
            float by = Bext[NCELL + g];
            float bz = Bext[2*NCELL + g];
            #pragma unroll
            for (int k = 0; k < 3; k++)
                if (gi == sp[2*k] && gj == sp[2*k+1]) bz += sv[k];
            Bx[q] = bx; By[q] = by; Bz[q] = bz;
            stg[0][0][cidx[q]] = mrx[q];
            stg[0][1][cidx[q]] = mry[q];
            stg[0][2][cidx[q]] = mrz[q];
        }
    }
    __syncthreads();

    // One RK4 stage: read stage field from stg[CUR], compute LLG torque k in
    // registers, write next stage field to stg[NXT], accumulate into acc.
    // RAD = region radius for this stage (3,2,1,0).
#define MM_STAGE(CUR, NXT, RAD, W, DO_NEXT, CNEXT)                                  \
    {                                                                               \
        _Pragma("unroll")                                                           \
        for (int q = 0; q < CPT; q++) {                                             \
            int li = li_[q], lj = lj_[q];                                           \
            bool act = ingrid[q] && li >= 4-(RAD) && li < TR+4+(RAD)                \
                                 && lj >= 4-(RAD) && lj < TC+4+(RAD);               \
            if (act) {                                                              \
                int ci = cidx[q];                                                   \
                float mx = stg[CUR][0][ci], my = stg[CUR][1][ci], mz = stg[CUR][2][ci]; \
                float lx = stg[CUR][0][nU[q]] + stg[CUR][0][nD[q]]                  \
                         + stg[CUR][0][nL[q]] + stg[CUR][0][nR[q]] - 4.0f*mx;       \
                float ly = stg[CUR][1][nU[q]] + stg[CUR][1][nD[q]]                  \
                         + stg[CUR][1][nL[q]] + stg[CUR][1][nR[q]] - 4.0f*my;       \
                float lz = stg[CUR][2][nU[q]] + stg[CUR][2][nD[q]]                  \
                         + stg[CUR][2][nL[q]] + stg[CUR][2][nR[q]] - 4.0f*mz;       \
                float bx = Bx[q] + cexch*lx;                                        \
                float by = By[q] + cexch*ly;                                        \
                float bz = Bz[q] + cexch*lz - cdem*mz;                              \
                float cx = my*bz - mz*by;                                           \
                float cy = mz*bx - mx*bz;                                           \
                float cz = mx*by - my*bx;                                           \
                float dx = my*cz - mz*cy;                                           \
                float dy = mz*cx - mx*cz;                                           \
                float dz = mx*cy - my*cx;                                           \
                float kx = pref*(cx + alpha*dx) + csot*(my*mx);                     \
                float ky = pref*(cy + alpha*dy) + csot*(mz*(-mz) - mx*mx);          \
                float kz = pref*(cz + alpha*dz) + csot*(my*mz);                     \
                if (DO_NEXT) {                                                      \
                    stg[NXT][0][ci] = mrx[q] + (CNEXT)*kx;                          \
                    stg[NXT][1][ci] = mry[q] + (CNEXT)*ky;                          \
                    stg[NXT][2][ci] = mrz[q] + (CNEXT)*kz;                          \
                }                                                                   \
                if (li >= 4 && li < TR+4 && lj >= 4 && lj < TC+4) {                 \
                    ax[q] += (W)*kx; ay[q] += (W)*ky; az[q] += (W)*kz;              \
                }                                                                   \
            }                                                                       \
        }                                                                           \
        __syncthreads();                                                            \
    }

    MM_STAGE(0, 1, 3, 1.0f, true,  ch)   // k1, m1 = m + 0.5h k1
    MM_STAGE(1, 0, 2, 2.0f, true,  ch)   // k2, m2 = m + 0.5h k2
    MM_STAGE(0, 1, 1, 2.0f, true,  hh)   // k3, m3 = m + h   k3
    MM_STAGE(1, 0, 0, 1.0f, false, 0.0f) // k4
#undef MM_STAGE

    // Combine + store + probes
    #pragma unroll
    for (int q = 0; q < CPT; q++) {
        int li = li_[q], lj = lj_[q];
        if (ingrid[q] && li >= 4 && li < TR+4 && lj >= 4 && lj < TC+4) {
            float mnx = mrx[q] + h6*ax[q];
            float mny = mry[q] + h6*ay[q];
            float mnz = mrz[q] + h6*az[q];
            int g = gidx[q];
            m_out[g]           = mnx;
            m_out[NCELL + g]   = mny;
            m_out[2*NCELL + g] = mnz;
            int gi = g >> 8, gj = g & 255;
            #pragma unroll
            for (int p = 0; p < 5; p++) {
                if (gi == probe_pos[2*p] && gj == probe_pos[2*p+1])
                    out[(s*TSTEPS + t)*5 + p] = mnz;
            }
        }
    }
}

extern "C" void kernel_launch(void* const* d_in, const int* in_sizes, int n_in,
                              void* d_out, int out_size) {
    const float* sig       = (const float*)d_in[0];  // list_signal (2,256,3)
    const float* Bext      = (const float*)d_in[1];  // (1,3,256,256)
    const float* Msat      = (const float*)d_in[2];  // scalar
    const int*   src_pos   = (const int*)d_in[3];    // (3,2)
    const int*   probe_pos = (const int*)d_in[4];    // (5,2)
    float*       out       = (float*)d_out;          // (2,256,5)

    mm_init_kernel<<<(NSIG*NCELL + 255)/256, 256>>>();

    dim3 grid(NYg/TC, NXg/TR, NSIG);   // (16, 8, 2) = 256 CTAs
    for (int t = 0; t < TSTEPS; t++) {
        mm_step_kernel<<<grid, NTH>>>(t & 1, t, sig, Bext, Msat,
                                      src_pos, probe_pos, out);
    }
}

// round 4
// speedup vs baseline: 1.1723x; 1.1723x over previous
#include <cuda_runtime.h>

#define NXg 256
#define NYg 256
#define NCELL (NXg*NYg)
#define TSTEPS 256
#define NSIG 2
#define TR 32            // tile rows (x / axis-2)
#define TC 16            // tile cols (y / axis-3)
#define ER (TR+8)        // 40
#define EC (TC+8)        // 24
#define EP 25            // padded SMEM pitch
#define NLOC (ER*EC)     // 960
#define NTH 256
#define CPT ((NLOC + NTH - 1)/NTH)   // 4
#define TILES_X (NXg/TR)             // 8
#define TILES_Y (NYg/TC)             // 16
#define NB (NSIG*TILES_X*TILES_Y)    // 256 CTAs — all co-resident (2/SM x 148 SMs)

// Ping-pong magnetization state: [buf][signal][component*NCELL + x*NY + y]
__device__ float g_state[2][NSIG][3*NCELL];
// grid barrier state (zero-initialized; returns to initial state after each run)
__device__ unsigned g_count;
__device__ volatile unsigned g_sense;

__global__ __launch_bounds__(NTH, 2) void mm_persist_kernel(
    const float* __restrict__ sig,        // (NSIG, TSTEPS, 3)
    const float* __restrict__ Bext,       // (1,3,NX,NY)
    const float* __restrict__ Msat_p,     // scalar
    const int*   __restrict__ src_pos,    // (3,2)
    const int*   __restrict__ probe_pos,  // (5,2)
    float*       __restrict__ out)        // (NSIG, TSTEPS, 5)
{
    __shared__ float stg[2][3][ER*EP];

    const int bid  = blockIdx.x;
    const int s    = bid / (TILES_X*TILES_Y);
    const int tile = bid % (TILES_X*TILES_Y);
    const int ti0  = (tile / TILES_Y) * TR;
    const int tj0  = (tile % TILES_Y) * TC;

    const float Msat  = Msat_p[0];
    const float cexch = 7.0e-12f / ((Msat * 5e-8f) * 5e-8f);  // 2*A/(Msat*dx^2)
    const float cdem  = 1.2566371e-06f * Msat;                // mu0*Msat (z-only demag)
    const float alpha = 0.01f;
    const float pref  = -1.0f / (1.0f + alpha*alpha);
    const float csot  = 1.0e-4f;
    const float hh    = 0.87975f;                 // GAMMA_LL*DT
    const float ch    = 0.439875f;                // 0.5*h
    const float h6    = (float)(0.87975/6.0);

    const int tid = threadIdx.x;

    int sp[6], pp[10];
    #pragma unroll
    for (int k = 0; k < 6; k++)  sp[k] = src_pos[k];
    #pragma unroll
    for (int k = 0; k < 10; k++) pp[k] = probe_pos[k];

    // -------- one-time per-cell setup (hoisted out of the 256-step loop) ------
    // mask bits: 0:rad3 1:rad2 2:rad1 3:interior 4:ingrid 5:rim
    //            8-11:srck+1  12-15:probe+1  16..19: clamp U/D/L/R at domain edge
    int   mask[CPT], cidx[CPT], gidx[CPT];
    float Bxv[CPT], Byv[CPT], Bzv[CPT];
    float mrx[CPT], mry[CPT], mrz[CPT];

    #pragma unroll
    for (int q = 0; q < CPT; q++) {
        int idx = tid + q*NTH;
        bool valid = idx < NLOC;
        int li = valid ? idx / EC : 0;
        int lj = valid ? idx % EC : 0;
        int gi = ti0 - 4 + li;
        int gj = tj0 - 4 + lj;
        bool ing = valid && gi >= 0 && gi < NXg && gj >= 0 && gj < NYg;
        int m = 0;
        cidx[q] = li*EP + lj;
        gidx[q] = gi*NYg + gj;
        Bxv[q] = Byv[q] = Bzv[q] = 0.0f;
        mrx[q] = 0.0f; mry[q] = 1.0f; mrz[q] = 0.0f;  // relaxed state == m0 exactly
        if (ing) {
            m |= 16;
            if (li >= 1 && li < TR+7 && lj >= 1 && lj < TC+7) m |= 1;
            if (li >= 2 && li < TR+6 && lj >= 2 && lj < TC+6) m |= 2;
            if (li >= 3 && li < TR+5 && lj >= 3 && lj < TC+5) m |= 4;
            if (li >= 4 && li < TR+4 && lj >= 4 && lj < TC+4) m |= 8; else m |= 32;
            if (gi == 0)      m |= 1<<16;
            if (gi == NXg-1)  m |= 1<<17;
            if (gj == 0)      m |= 1<<18;
            if (gj == NYg-1)  m |= 1<<19;
            #pragma unroll
            for (int k = 0; k < 3; k++)
                if (gi == sp[2*k] && gj == sp[2*k+1]) m |= (k+1) << 8;
            #pragma unroll
            for (int p = 0; p < 5; p++)
                if (gi == pp[2*p] && gj == pp[2*p+1]) m |= (p+1) << 12;
            int g = gidx[q];
            Bxv[q] = Bext[g];
            Byv[q] = Bext[NCELL + g];
            Bzv[q] = Bext[2*NCELL + g];
        }
        mask[q] = m;
    }

    // -------- time loop: 256 RK4 steps, one grid barrier each ---------------
    for (int t = 0; t < TSTEPS; t++) {
        const float* __restrict__ bin  = g_state[t & 1][s];
        float*       __restrict__ bout = g_state[(t & 1) ^ 1][s];

        float sadd[CPT];
        float smx[CPT], smy[CPT], smz[CPT];
        float ax[CPT], ay[CPT], az[CPT];

        #pragma unroll
        for (int q = 0; q < CPT; q++) {
            int m = mask[q];
            if (t > 0 && (m & 32)) {          // rim refresh from neighbor tiles (L2)
                int g = gidx[q];
                mrx[q] = __ldcg(&bin[g]);
                mry[q] = __ldcg(&bin[NCELL + g]);
                mrz[q] = __ldcg(&bin[2*NCELL + g]);
            }
            int sk = (m >> 8) & 15;
            sadd[q] = sk ? __ldg(&sig[(s*TSTEPS + t)*3 + (sk-1)]) : 0.0f;
            smx[q] = mrx[q]; smy[q] = mry[q]; smz[q] = mrz[q];
            if (m & 16) {
                int ci = cidx[q];
                stg[0][0][ci] = mrx[q];
                stg[0][1][ci] = mry[q];
                stg[0][2][ci] = mrz[q];
            }
            ax[q] = ay[q] = az[q] = 0.0f;
        }
        __syncthreads();

        // One RK4 stage: centers in registers (sm*), neighbors from stg[CUR].
#define MM_STAGE(CUR, NXT, BIT, W, DO_NEXT, CNEXT)                                  \
        {                                                                           \
            _Pragma("unroll")                                                       \
            for (int q = 0; q < CPT; q++) {                                         \
                int m = mask[q];                                                    \
                if (m & (BIT)) {                                                    \
                    int ci = cidx[q];                                               \
                    int iu = ci - ((m & (1<<16)) ? 0 : EP);                         \
                    int id = ci + ((m & (1<<17)) ? 0 : EP);                         \
                    int il = ci - ((m & (1<<18)) ? 0 : 1);                          \
                    int ir = ci + ((m & (1<<19)) ? 0 : 1);                          \
                    float mx = smx[q], my = smy[q], mz = smz[q];                    \
                    float lx = stg[CUR][0][iu] + stg[CUR][0][id]                    \
                             + stg[CUR][0][il] + stg[CUR][0][ir] - 4.0f*mx;         \
                    float ly = stg[CUR][1][iu] + stg[CUR][1][id]                    \
                             + stg[CUR][1][il] + stg[CUR][1][ir] - 4.0f*my;         \
                    float lz = stg[CUR][2][iu] + stg[CUR][2][id]                    \
                             + stg[CUR][2][il] + stg[CUR][2][ir] - 4.0f*mz;         \
                    float bx = Bxv[q] + cexch*lx;                                   \
                    float by = Byv[q] + cexch*ly;                                   \
                    float bz = Bzv[q] + sadd[q] + cexch*lz - cdem*mz;               \
                    float cx = my*bz - mz*by;                                       \
                    float cy = mz*bx - mx*bz;                                       \
                    float cz = mx*by - my*bx;                                       \
                    float dx = my*cz - mz*cy;                                       \
                    float dy = mz*cx - mx*cz;                                       \
                    float dz = mx*cy - my*cx;                                       \
                    float kx = pref*(cx + alpha*dx) + csot*(my*mx);                 \
                    float ky = pref*(cy + alpha*dy) + csot*(mz*(-mz) - mx*mx);      \
                    float kz = pref*(cz + alpha*dz) + csot*(my*mz);                 \
                    if (DO_NEXT) {                                                  \
                        float nx2 = mrx[q] + (CNEXT)*kx;                            \
                        float ny2 = mry[q] + (CNEXT)*ky;                            \
                        float nz2 = mrz[q] + (CNEXT)*kz;                            \
                        smx[q] = nx2; smy[q] = ny2; smz[q] = nz2;                   \
                        stg[NXT][0][ci] = nx2;                                      \
                        stg[NXT][1][ci] = ny2;                                      \
                        stg[NXT][2][ci] = nz2;                                      \
                    }                                                               \
                    if (m & 8) { ax[q] += (W)*kx; ay[q] += (W)*ky; az[q] += (W)*kz; } \
                }                                                                   \
            }                                                                       \
            __syncthreads();                                                        \
        }

        MM_STAGE(0, 1, 1, 1.0f, true,  ch)   // k1 -> m + 0.5h k1
        MM_STAGE(1, 0, 2, 2.0f, true,  ch)   // k2 -> m + 0.5h k2
        MM_STAGE(0, 1, 4, 2.0f, true,  hh)   // k3 -> m + h   k3
        MM_STAGE(1, 0, 8, 1.0f, false, 0.0f) // k4
#undef MM_STAGE

        // combine, store interior, probes
        #pragma unroll
        for (int q = 0; q < CPT; q++) {
            int m = mask[q];
            if (m & 8) {
                float mnx = mrx[q] + h6*ax[q];
                float mny = mry[q] + h6*ay[q];
                float mnz = mrz[q] + h6*az[q];
                mrx[q] = mnx; mry[q] = mny; mrz[q] = mnz;   // interior stays in regs
                int g = gidx[q];
                __stcg(&bout[g],           mnx);
                __stcg(&bout[NCELL + g],   mny);
                __stcg(&bout[2*NCELL + g], mnz);
                int pr = (m >> 12) & 15;
                if (pr) out[(s*TSTEPS + t)*5 + (pr-1)] = mnz;
            }
        }

        // ---- grid barrier (sense = monotonic generation t+1) ----
        __threadfence();          // every thread: make bout stores visible gpu-wide
        __syncthreads();
        if (tid == 0) {
            unsigned target = (unsigned)(t + 1);
            if (atomicAdd(&g_count, 1u) == NB - 1) {
                g_count = 0;
                __threadfence();
                g_sense = target;
            } else {
                while (g_sense != target) __nanosleep(64);
            }
        }
        __syncthreads();
    }
}

extern "C" void kernel_launch(void* const* d_in, const int* in_sizes, int n_in,
                              void* d_out, int out_size) {
    const float* sig       = (const float*)d_in[0];  // (2,256,3)
    const float* Bext      = (const float*)d_in[1];  // (1,3,256,256)
    const float* Msat      = (const float*)d_in[2];  // scalar
    const int*   src_pos   = (const int*)d_in[3];    // (3,2)
    const int*   probe_pos = (const int*)d_in[4];    // (5,2)
    float*       out       = (float*)d_out;          // (2,256,5)

    mm_persist_kernel<<<NB, NTH>>>(sig, Bext, Msat, src_pos, probe_pos, out);
}

// round 5
// speedup vs baseline: 1.2296x; 1.0489x over previous
#include <cuda_runtime.h>

#define NXg 256
#define NYg 256
#define NCELL (NXg*NYg)
#define TSTEPS 256
#define NSIG 2
#define TR 32            // tile rows (x)
#define TC 16            // tile cols (y)
#define ER 40            // ext rows = TR+8
#define EC 24            // ext cols = TC+8
#define EPP 28           // smem pitch: 2 left guard + 24 + 2 right guard (even -> float2 aligned)
#define SROWS 42         // 1 top guard + 40 + 1 bottom guard
#define ROW0 1
#define COL0 2
#define NTH 256
#define NBLK 240         // 20 x 12 blocks of 2x2 cells
#define BPR 12           // blocks per row
#define TILES_X 8
#define TILES_Y 16
#define NB 256           // CTAs (all co-resident: 2/SM x 148 SMs >= 256)

// Ping-pong magnetization state (only interior band cells ever written/read)
__device__ float g_state[2][NSIG][3*NCELL];
// grid barrier (zero-init; g_count returns to 0 every step)
__device__ unsigned g_count;
__device__ volatile unsigned g_sense;

__global__ __launch_bounds__(NTH, 2) void mm_persist_kernel(
    const float* __restrict__ sig,        // (NSIG, TSTEPS, 3)
    const float* __restrict__ Bext,       // (1,3,NX,NY)
    const float* __restrict__ Msat_p,     // scalar
    const int*   __restrict__ src_pos,    // (3,2)
    const int*   __restrict__ probe_pos,  // (5,2)
    float*       __restrict__ out)        // (NSIG, TSTEPS, 5)
{
    __shared__ float stg[2][3][SROWS*EPP];

    const int tid = threadIdx.x;
    const int bid = blockIdx.x;
    const int s    = bid / (TILES_X*TILES_Y);
    const int tile = bid % (TILES_X*TILES_Y);
    const int ti0  = (tile / TILES_Y) * TR;
    const int tj0  = (tile % TILES_Y) * TC;

    // zero smem once (guard-ring hygiene: garbage must be finite-only-read; zero is safest)
    for (int i = tid; i < 2*3*SROWS*EPP; i += NTH)
        ((float*)stg)[i] = 0.0f;

    const float Msat  = Msat_p[0];
    const float cexch = 7.0e-12f / ((Msat * 5e-8f) * 5e-8f);  // 2*A/(Msat*dx^2)
    const float cdem  = 1.2566371e-06f * Msat;                // mu0*Msat (z demag)
    const float alpha = 0.01f;
    const float pref  = -1.0f / (1.0f + alpha*alpha);
    const float csot  = 1.0e-4f;
    const float hh    = 0.87975f;                 // GAMMA_LL*DT
    const float ch    = 0.439875f;                // 0.5*h
    const float h6    = (float)(0.87975/6.0);

    const bool active = tid < NBLK;
    const int  br  = tid / BPR;
    const int  bc  = tid - br*BPR;
    const int  li0 = 2*br, lj0 = 2*bc;
    const int  gi0 = ti0 - 4 + li0;
    const int  gj0 = tj0 - 4 + lj0;
    // blocks are fully in-grid or fully out per dimension (all offsets even)
    const bool ing = active && gi0 >= 0 && gi0 <= NXg-2 && gj0 >= 0 && gj0 <= NYg-2;
    const bool interior_blk = active && br >= 2 && br < 18 && bc >= 2 && bc < 10;
    const bool deep = br >= 4 && br < 16 && bc >= 4 && bc < 8;
    const bool band = interior_blk && !deep;      // 4-wide ring of interior: rim provider
    const bool rim  = active && ing && !interior_blk;

    // smem indices (with domain-edge clamp folded in)
    const int  B0  = (ROW0 + li0)*EPP + (COL0 + lj0);
    const bool clU = (gi0 == 0), clD = (gi0+1 == NXg-1);
    const bool clL = (gj0 == 0), clR = (gj0+1 == NYg-1);
    const int  iU  = clU ? B0 : B0 - EPP;          // up pair (float2)
    const int  iD  = clD ? B0 + EPP : B0 + 2*EPP;  // down pair (float2)
    const int  iLt = clL ? B0 : B0 - 1;
    const int  iLb = iLt + EPP;
    const int  iRt = clR ? B0 + 1 : B0 + 2;
    const int  iRb = iRt + EPP;
    const int  g0  = gi0*NYg + gj0;

    // per-cell constants (cells: 0=(0,0) 1=(0,1) 2=(1,0) 3=(1,1) within block)
    float Bfx[4] = {0,0,0,0}, Bfy[4] = {0,0,0,0}, Bzv[4] = {0,0,0,0};
    float mr[3][4];
    #pragma unroll
    for (int c = 0; c < 4; c++) { mr[0][c] = 0.0f; mr[1][c] = 1.0f; mr[2][c] = 0.0f; }
    int srcf = 0, prf = 0;   // 4-bit fields per cell

    if (ing) {
        int sp[6], pp[10];
        #pragma unroll
        for (int k = 0; k < 6; k++)  sp[k] = src_pos[k];
        #pragma unroll
        for (int k = 0; k < 10; k++) pp[k] = probe_pos[k];
        #pragma unroll
        for (int c = 0; c < 4; c++) {
            int gi = gi0 + (c >> 1), gj = gj0 + (c & 1);
            int g  = gi*NYg + gj;
            Bfx[c] = Bext[g];
            Bfy[c] = Bext[NCELL + g];
            Bzv[c] = Bext[2*NCELL + g];
            #pragma unroll
            for (int k = 0; k < 3; k++)
                if (gi == sp[2*k] && gj == sp[2*k+1]) srcf |= (k+1) << (4*c);
            #pragma unroll
            for (int p = 0; p < 5; p++)
                if (gi == pp[2*p] && gj == pp[2*p+1]) prf |= (p+1) << (4*c);
        }
    }

    float sm[3][4], a[3][4], bzt[4];

    for (int t = 0; t < TSTEPS; t++) {
        const float* __restrict__ bin  = g_state[t & 1][s];
        float*       __restrict__ bout = g_state[(t & 1) ^ 1][s];

        // rim refresh from neighbor tiles' band stores (L2-coherent)
        if (rim && t > 0) {
            float2 v;
            v = __ldcg((const float2*)&bin[g0]);             mr[0][0]=v.x; mr[0][1]=v.y;
            v = __ldcg((const float2*)&bin[g0+NYg]);         mr[0][2]=v.x; mr[0][3]=v.y;
            v = __ldcg((const float2*)&bin[NCELL+g0]);       mr[1][0]=v.x; mr[1][1]=v.y;
            v = __ldcg((const float2*)&bin[NCELL+g0+NYg]);   mr[1][2]=v.x; mr[1][3]=v.y;
            v = __ldcg((const float2*)&bin[2*NCELL+g0]);     mr[2][0]=v.x; mr[2][1]=v.y;
            v = __ldcg((const float2*)&bin[2*NCELL+g0+NYg]); mr[2][2]=v.x; mr[2][3]=v.y;
        }

        if (active) {
            #pragma unroll
            for (int c = 0; c < 4; c++) {
                int k = (srcf >> (4*c)) & 15;
                bzt[c] = Bzv[c] + (k ? __ldg(&sig[(s*TSTEPS + t)*3 + (k-1)]) : 0.0f);
                sm[0][c] = mr[0][c]; sm[1][c] = mr[1][c]; sm[2][c] = mr[2][c];
                a[0][c] = 0.0f; a[1][c] = 0.0f; a[2][c] = 0.0f;
            }
            #pragma unroll
            for (int X = 0; X < 3; X++) {
                *(float2*)&stg[0][X][B0]       = make_float2(sm[X][0], sm[X][1]);
                *(float2*)&stg[0][X][B0+EPP]   = make_float2(sm[X][2], sm[X][3]);
            }
        }
        __syncthreads();

        // One RK4 stage, computed for ALL blocks unconditionally (garbage at ext
        // ring r propagates 1 ring/stage; never reaches interior ring >= 4).
#define MM_STAGE(CUR, NXT, W, DO_NEXT, CNEXT)                                       \
        if (active) {                                                               \
            float lap[3][4];                                                        \
            _Pragma("unroll")                                                       \
            for (int X = 0; X < 3; X++) {                                           \
                const float* S = stg[CUR][X];                                       \
                float2 u  = *(const float2*)&S[iU];                                 \
                float2 dn = *(const float2*)&S[iD];                                 \
                float lt = S[iLt], lb = S[iLb], rt2 = S[iRt], rb = S[iRb];          \
                lap[X][0] = u.x      + sm[X][2] + lt       + sm[X][1] - 4.0f*sm[X][0]; \
                lap[X][1] = u.y      + sm[X][3] + sm[X][0] + rt2      - 4.0f*sm[X][1]; \
                lap[X][2] = sm[X][0] + dn.x     + lb       + sm[X][3] - 4.0f*sm[X][2]; \
                lap[X][3] = sm[X][1] + dn.y     + sm[X][2] + rb       - 4.0f*sm[X][3]; \
            }                                                                       \
            _Pragma("unroll")                                                       \
            for (int c = 0; c < 4; c++) {                                           \
                float mx = sm[0][c], my = sm[1][c], mz = sm[2][c];                  \
                float bx = Bfx[c] + cexch*lap[0][c];                                \
                float by = Bfy[c] + cexch*lap[1][c];                                \
                float bz = bzt[c] + cexch*lap[2][c] - cdem*mz;                      \
                float cx = my*bz - mz*by;                                           \
                float cy = mz*bx - mx*bz;                                           \
                float cz = mx*by - my*bx;                                           \
                float dx = my*cz - mz*cy;                                           \
                float dy = mz*cx - mx*cz;                                           \
                float dz = mx*cy - my*cx;                                           \
                float kx = pref*(cx + alpha*dx) + csot*(my*mx);                     \
                float ky = pref*(cy + alpha*dy) + csot*(mz*(-mz) - mx*mx);          \
                float kz = pref*(cz + alpha*dz) + csot*(my*mz);                     \
                if (DO_NEXT) {                                                      \
                    sm[0][c] = mr[0][c] + (CNEXT)*kx;                               \
                    sm[1][c] = mr[1][c] + (CNEXT)*ky;                               \
                    sm[2][c] = mr[2][c] + (CNEXT)*kz;                               \
                }                                                                   \
                a[0][c] += (W)*kx; a[1][c] += (W)*ky; a[2][c] += (W)*kz;            \
            }                                                                       \
            if (DO_NEXT) {                                                          \
                _Pragma("unroll")                                                   \
                for (int X = 0; X < 3; X++) {                                       \
                    *(float2*)&stg[NXT][X][B0]     = make_float2(sm[X][0], sm[X][1]); \
                    *(float2*)&stg[NXT][X][B0+EPP] = make_float2(sm[X][2], sm[X][3]); \
                }                                                                   \
            }                                                                       \
        }                                                                           \
        __syncthreads();

        MM_STAGE(0, 1, 1.0f, true,  ch)   // k1 -> m + 0.5h k1
        MM_STAGE(1, 0, 2.0f, true,  ch)   // k2 -> m + 0.5h k2
        MM_STAGE(0, 1, 2.0f, true,  hh)   // k3 -> m + h   k3
        MM_STAGE(1, 0, 1.0f, false, 0.0f) // k4
#undef MM_STAGE

        // combine; interior state stays in registers; only band goes to global
        if (interior_blk) {
            #pragma unroll
            for (int c = 0; c < 4; c++) {
                mr[0][c] += h6*a[0][c];
                mr[1][c] += h6*a[1][c];
                mr[2][c] += h6*a[2][c];
            }
            if (band) {
                __stcg((float2*)&bout[g0],             make_float2(mr[0][0], mr[0][1]));
                __stcg((float2*)&bout[g0+NYg],         make_float2(mr[0][2], mr[0][3]));
                __stcg((float2*)&bout[NCELL+g0],       make_float2(mr[1][0], mr[1][1]));
                __stcg((float2*)&bout[NCELL+g0+NYg],   make_float2(mr[1][2], mr[1][3]));
                __stcg((float2*)&bout[2*NCELL+g0],     make_float2(mr[2][0], mr[2][1]));
                __stcg((float2*)&bout[2*NCELL+g0+NYg], make_float2(mr[2][2], mr[2][3]));
            }
            if (prf) {
                #pragma unroll
                for (int c = 0; c < 4; c++) {
                    int p = (prf >> (4*c)) & 15;
                    if (p) out[(s*TSTEPS + t)*5 + (p-1)] = mr[2][c];
                }
            }
        }

        // grid barrier (monotonic generation t+1; safe across graph replays)
        __threadfence();
        __syncthreads();
        if (tid == 0) {
            unsigned target = (unsigned)(t + 1);
            if (atomicAdd(&g_count, 1u) == NB - 1) {
                g_count = 0;
                __threadfence();
                g_sense = target;
            } else {
                while (g_sense != target) { }
                __threadfence();
            }
        }
        __syncthreads();
    }
}

extern "C" void kernel_launch(void* const* d_in, const int* in_sizes, int n_in,
                              void* d_out, int out_size) {
    const float* sig       = (const float*)d_in[0];  // (2,256,3)
    const float* Bext      = (const float*)d_in[1];  // (1,3,256,256)
    const float* Msat      = (const float*)d_in[2];  // scalar
    const int*   src_pos   = (const int*)d_in[3];    // (3,2)
    const int*   probe_pos = (const int*)d_in[4];    // (5,2)
    float*       out       = (float*)d_out;          // (2,256,5)

    mm_persist_kernel<<<NB, NTH>>>(sig, Bext, Msat, src_pos, probe_pos, out);
}

// round 7
// speedup vs baseline: 1.2848x; 1.0449x over previous
#include <cuda_runtime.h>

typedef unsigned long long u64;

#define NXg 256
#define NYg 256
#define NCELL (NXg*NYg)
#define TSTEPS 256
#define NSIG 2
#define TR 32            // tile rows (x)
#define TC 16            // tile cols (y)
#define EPP 28           // smem pitch: 2 left guard + 24 + 2 right guard
#define SROWS 42         // 1 top guard + 40 + 1 bottom guard
#define ROW0 1
#define COL0 2
#define NTH 256
#define NBLK 240         // 20 x 12 blocks of 2x2 cells
#define BPR 12
#define TILES_X 8
#define TILES_Y 16
#define NBS (TILES_X*TILES_Y)   // 128 CTAs per signal
#define NB (NSIG*NBS)           // 256 CTAs total, all co-resident

// Ping-pong magnetization state (only interior band cells ever written/read)
__device__ __align__(16) float g_state[2][NSIG][3*NCELL];
// per-signal grid barrier (zero-init; count returns to 0; sense exact-match is replay-safe)
__device__ unsigned g_cnt[NSIG];
__device__ volatile unsigned g_sns[NSIG];

// ---- packed f32x2 helpers (SASS FFMA2/FADD2/FMUL2; only reachable via PTX) ----
static __device__ __forceinline__ u64 pk2(float lo, float hi) {
    u64 r; asm("mov.b64 %0,{%1,%2};" : "=l"(r) : "f"(lo), "f"(hi)); return r;
}
static __device__ __forceinline__ void upk2(u64 v, float &lo, float &hi) {
    asm("mov.b64 {%0,%1}, %2;" : "=f"(lo), "=f"(hi) : "l"(v));
}
static __device__ __forceinline__ u64 f2add(u64 a, u64 b) {
    u64 r; asm("add.rn.f32x2 %0,%1,%2;" : "=l"(r) : "l"(a), "l"(b)); return r;
}
static __device__ __forceinline__ u64 f2mul(u64 a, u64 b) {
    u64 r; asm("mul.rn.f32x2 %0,%1,%2;" : "=l"(r) : "l"(a), "l"(b)); return r;
}
static __device__ __forceinline__ u64 f2fma(u64 a, u64 b, u64 c) {
    u64 r; asm("fma.rn.f32x2 %0,%1,%2,%3;" : "=l"(r) : "l"(a), "l"(b), "l"(c)); return r;
}

__global__ __launch_bounds__(NTH, 2) void mm_persist_kernel(
    const float* __restrict__ sig,        // (NSIG, TSTEPS, 3)
    const float* __restrict__ Bext,       // (1,3,NX,NY)
    const float* __restrict__ Msat_p,     // scalar
    const int*   __restrict__ src_pos,    // (3,2)
    const int*   __restrict__ probe_pos,  // (5,2)
    float*       __restrict__ out)        // (NSIG, TSTEPS, 5)
{
    __shared__ __align__(16) float stg[2][3][SROWS*EPP];

    const int tid = threadIdx.x;
    const int bid = blockIdx.x;
    const int s    = bid / NBS;
    const int tile = bid % NBS;
    const int ti0  = (tile / TILES_Y) * TR;
    const int tj0  = (tile % TILES_Y) * TC;

    // zero smem once (guard-ring hygiene)
    for (int i = tid; i < 2*3*SROWS*EPP; i += NTH)
        ((float*)stg)[i] = 0.0f;

    const float Msat  = Msat_p[0];
    const float cexch = 7.0e-12f / ((Msat * 5e-8f) * 5e-8f);
    const float cdem  = 1.2566371e-06f * Msat;
    const float alpha = 0.01f;
    const float pref  = -1.0f / (1.0f + alpha*alpha);

    // packed coefficient registers
    const u64 C_M4   = pk2(-4.0f, -4.0f);
    const u64 C_EXCH = pk2(cexch, cexch);
    const u64 C_NDEM = pk2(-cdem, -cdem);
    const u64 C_NEG1 = pk2(-1.0f, -1.0f);
    const u64 C_PREF = pk2(pref, pref);
    const u64 C_ALPH = pk2(alpha, alpha);
    const u64 C_SOT  = pk2(1.0e-4f, 1.0e-4f);
    const u64 C_TWO  = pk2(2.0f, 2.0f);
    const u64 C_CH   = pk2(0.439875f, 0.439875f);       // 0.5*h
    const u64 C_HH   = pk2(0.87975f, 0.87975f);         // h
    const u64 C_H6   = pk2((float)(0.87975/6.0), (float)(0.87975/6.0));

    const bool active = tid < NBLK;
    const int  br  = tid / BPR;
    const int  bc  = tid - br*BPR;
    const int  li0 = 2*br, lj0 = 2*bc;
    const int  gi0 = ti0 - 4 + li0;
    const int  gj0 = tj0 - 4 + lj0;
    const bool ing = active && gi0 >= 0 && gi0 <= NXg-2 && gj0 >= 0 && gj0 <= NYg-2;
    const bool interior_blk = active && br >= 2 && br < 18 && bc >= 2 && bc < 10;
    const bool deep = br >= 4 && br < 16 && bc >= 4 && bc < 8;
    const bool band = interior_blk && !deep;
    const bool rim  = active && ing && !interior_blk;

    const int  B0  = (ROW0 + li0)*EPP + (COL0 + lj0);
    const bool clU = (gi0 == 0), clD = (gi0+1 == NXg-1);
    const bool clL = (gj0 == 0), clR = (gj0+1 == NYg-1);
    const int  iU  = clU ? B0 : B0 - EPP;
    const int  iD  = clD ? B0 + EPP : B0 + 2*EPP;
    const int  iLt = clL ? B0 : B0 - 1;
    const int  iLb = iLt + EPP;
    const int  iRt = clR ? B0 + 1 : B0 + 2;
    const int  iRb = iRt + EPP;
    const int  g0  = gi0*NYg + gj0;

    // packed per-pair state: pair01 = cells (0,1) = row gi0; pair23 = row gi0+1
    u64 MR01[3], MR23[3];             // committed m
    u64 M01[3],  M23[3];              // stage m
    u64 A01[3],  A23[3];              // RK accumulators
    u64 BF01x = 0, BF01y = 0, BZ01 = 0;
    u64 BF23x = 0, BF23y = 0, BZ23 = 0;
    u64 BZT01 = 0, BZT23 = 0;
    MR01[0] = 0; MR01[1] = pk2(1.0f, 1.0f); MR01[2] = 0;
    MR23[0] = 0; MR23[1] = pk2(1.0f, 1.0f); MR23[2] = 0;
    int srcf = 0, prf = 0;

    if (ing) {
        int sp[6], pp[10];
        #pragma unroll
        for (int k = 0; k < 6; k++)  sp[k] = src_pos[k];
        #pragma unroll
        for (int k = 0; k < 10; k++) pp[k] = probe_pos[k];
        float2 v;
        v = *(const float2*)&Bext[g0];              BF01x = pk2(v.x, v.y);
        v = *(const float2*)&Bext[g0+NYg];          BF23x = pk2(v.x, v.y);
        v = *(const float2*)&Bext[NCELL+g0];        BF01y = pk2(v.x, v.y);
        v = *(const float2*)&Bext[NCELL+g0+NYg];    BF23y = pk2(v.x, v.y);
        v = *(const float2*)&Bext[2*NCELL+g0];      BZ01  = pk2(v.x, v.y);
        v = *(const float2*)&Bext[2*NCELL+g0+NYg];  BZ23  = pk2(v.x, v.y);
        #pragma unroll
        for (int c = 0; c < 4; c++) {
            int gi = gi0 + (c >> 1), gj = gj0 + (c & 1);
            #pragma unroll
            for (int k = 0; k < 3; k++)
                if (gi == sp[2*k] && gj == sp[2*k+1]) srcf |= (k+1) << (4*c);
            #pragma unroll
            for (int p = 0; p < 5; p++)
                if (gi == pp[2*p] && gj == pp[2*p+1]) prf |= (p+1) << (4*c);
        }
    }

    // initial stg[0] fill (t=0 stage field)
    if (active) {
        #pragma unroll
        for (int X = 0; X < 3; X++) {
            *(u64*)&stg[0][X][B0]     = MR01[X];
            *(u64*)&stg[0][X][B0+EPP] = MR23[X];
        }
    }

    for (int t = 0; t < TSTEPS; t++) {
        const float* __restrict__ bin  = g_state[t & 1][s];
        float*       __restrict__ bout = g_state[(t & 1) ^ 1][s];

        // rim refresh from neighbor tiles (L2), and rim stg[0] fill
        if (rim && t > 0) {
            MR01[0] = __ldcg((const u64*)&bin[g0]);
            MR23[0] = __ldcg((const u64*)&bin[g0+NYg]);
            MR01[1] = __ldcg((const u64*)&bin[NCELL+g0]);
            MR23[1] = __ldcg((const u64*)&bin[NCELL+g0+NYg]);
            MR01[2] = __ldcg((const u64*)&bin[2*NCELL+g0]);
            MR23[2] = __ldcg((const u64*)&bin[2*NCELL+g0+NYg]);
            #pragma unroll
            for (int X = 0; X < 3; X++) {
                *(u64*)&stg[0][X][B0]     = MR01[X];
                *(u64*)&stg[0][X][B0+EPP] = MR23[X];
            }
        }

        if (active) {
            if (srcf) {
                const float* sgp = &sig[(s*TSTEPS + t)*3];
                float sa[4];
                #pragma unroll
                for (int c = 0; c < 4; c++) {
                    int k = (srcf >> (4*c)) & 15;
                    sa[c] = k ? __ldg(&sgp[k-1]) : 0.0f;
                }
                BZT01 = f2add(BZ01, pk2(sa[0], sa[1]));
                BZT23 = f2add(BZ23, pk2(sa[2], sa[3]));
            } else {
                BZT01 = BZ01; BZT23 = BZ23;
            }
            #pragma unroll
            for (int X = 0; X < 3; X++) {
                M01[X] = MR01[X]; M23[X] = MR23[X];
                A01[X] = 0;       A23[X] = 0;
            }
        }
        __syncthreads();

        // One RK4 stage for all blocks (guard-ring garbage never reaches interior).
#define MM_STAGE(CUR, NXT, WISONE, DO_NEXT, C2)                                     \
        if (active) {                                                               \
            u64 LAP01[3], LAP23[3];                                                 \
            _Pragma("unroll")                                                       \
            for (int X = 0; X < 3; X++) {                                           \
                const float* Sp = stg[CUR][X];                                      \
                u64 U01 = *(const u64*)&Sp[iU];                                     \
                u64 D23 = *(const u64*)&Sp[iD];                                     \
                float lt = Sp[iLt], lb = Sp[iLb], rt = Sp[iRt], rb = Sp[iRb];       \
                float m0, m1, m2, m3;                                               \
                upk2(M01[X], m0, m1); upk2(M23[X], m2, m3);                         \
                u64 s01 = f2add(f2add(f2add(U01, M23[X]), pk2(lt, m0)), pk2(m1, rt)); \
                u64 s23 = f2add(f2add(f2add(M01[X], D23), pk2(lb, m2)), pk2(m3, rb)); \
                LAP01[X] = f2fma(M01[X], C_M4, s01);                                \
                LAP23[X] = f2fma(M23[X], C_M4, s23);                                \
            }                                                                       \
            _Pragma("unroll")                                                       \
            for (int P = 0; P < 2; P++) {                                           \
                u64* Mv  = P ? M23  : M01;                                          \
                u64* MRv = P ? MR23 : MR01;                                         \
                u64* Av  = P ? A23  : A01;                                          \
                u64* LAP = P ? LAP23 : LAP01;                                       \
                u64 bfx = P ? BF23x : BF01x;                                        \
                u64 bfy = P ? BF23y : BF01y;                                        \
                u64 bzt = P ? BZT23 : BZT01;                                        \
                u64 bx = f2fma(LAP[0], C_EXCH, bfx);                                \
                u64 by = f2fma(LAP[1], C_EXCH, bfy);                                \
                u64 bz = f2fma(Mv[2], C_NDEM, f2fma(LAP[2], C_EXCH, bzt));          \
                u64 n0 = f2mul(Mv[0], C_NEG1);                                      \
                u64 n1 = f2mul(Mv[1], C_NEG1);                                      \
                u64 n2 = f2mul(Mv[2], C_NEG1);                                      \
                u64 cx = f2fma(Mv[1], bz, f2mul(n2, by));                           \
                u64 cy = f2fma(Mv[2], bx, f2mul(n0, bz));                           \
                u64 cz = f2fma(Mv[0], by, f2mul(n1, bx));                           \
                u64 dx = f2fma(Mv[1], cz, f2mul(n2, cy));                           \
                u64 dy = f2fma(Mv[2], cx, f2mul(n0, cz));                           \
                u64 dz = f2fma(Mv[0], cy, f2mul(n1, cx));                           \
                u64 kx = f2fma(C_SOT, f2mul(Mv[1], Mv[0]),                          \
                               f2mul(C_PREF, f2fma(C_ALPH, dx, cx)));               \
                u64 ky = f2fma(C_SOT, f2fma(n0, Mv[0], f2mul(n2, Mv[2])),           \
                               f2mul(C_PREF, f2fma(C_ALPH, dy, cy)));               \
                u64 kz = f2fma(C_SOT, f2mul(Mv[1], Mv[2]),                          \
                               f2mul(C_PREF, f2fma(C_ALPH, dz, cz)));               \
                if (WISONE) {                                                       \
                    Av[0] = f2add(Av[0], kx);                                       \
                    Av[1] = f2add(Av[1], ky);                                       \
                    Av[2] = f2add(Av[2], kz);                                       \
                } else {                                                            \
                    Av[0] = f2fma(kx, C_TWO, Av[0]);                                \
                    Av[1] = f2fma(ky, C_TWO, Av[1]);                                \
                    Av[2] = f2fma(kz, C_TWO, Av[2]);                                \
                }                                                                   \
                if (DO_NEXT) {                                                      \
                    Mv[0] = f2fma(kx, C2, MRv[0]);                                  \
                    Mv[1] = f2fma(ky, C2, MRv[1]);                                  \
                    Mv[2] = f2fma(kz, C2, MRv[2]);                                  \
                }                                                                   \
            }                                                                       \
            if (DO_NEXT) {                                                          \
                _Pragma("unroll")                                                   \
                for (int X = 0; X < 3; X++) {                                       \
                    *(u64*)&stg[NXT][X][B0]     = M01[X];                           \
                    *(u64*)&stg[NXT][X][B0+EPP] = M23[X];                           \
                }                                                                   \
            }                                                                       \
        }                                                                           \
        if (DO_NEXT) __syncthreads();

        MM_STAGE(0, 1, true,  true,  C_CH)   // k1 -> m + 0.5h k1
        MM_STAGE(1, 0, false, true,  C_CH)   // k2 -> m + 0.5h k2
        MM_STAGE(0, 1, false, true,  C_HH)   // k3 -> m + h   k3
        MM_STAGE(1, 0, true,  false, C_CH)   // k4 (no next field, no sync: reads stg[1] only)
#undef MM_STAGE

        // combine; interior stays in regs; stg[0] pre-filled for next step (stg[0] is
        // dead after k2; k4 reads stg[1] only, so no sync needed before these writes)
        if (interior_blk) {
            #pragma unroll
            for (int X = 0; X < 3; X++) {
                MR01[X] = f2fma(A01[X], C_H6, MR01[X]);
                MR23[X] = f2fma(A23[X], C_H6, MR23[X]);
                *(u64*)&stg[0][X][B0]     = MR01[X];
                *(u64*)&stg[0][X][B0+EPP] = MR23[X];
            }
            if (band) {
                __stcg((u64*)&bout[g0],             MR01[0]);
                __stcg((u64*)&bout[g0+NYg],         MR23[0]);
                __stcg((u64*)&bout[NCELL+g0],       MR01[1]);
                __stcg((u64*)&bout[NCELL+g0+NYg],   MR23[1]);
                __stcg((u64*)&bout[2*NCELL+g0],     MR01[2]);
                __stcg((u64*)&bout[2*NCELL+g0+NYg], MR23[2]);
            }
            if (prf) {
                float z0, z1, z2, z3;
                upk2(MR01[2], z0, z1); upk2(MR23[2], z2, z3);
                float zz[4] = {z0, z1, z2, z3};
                #pragma unroll
                for (int c = 0; c < 4; c++) {
                    int p = (prf >> (4*c)) & 15;
                    if (p) out[(s*TSTEPS + t)*5 + (p-1)] = zz[c];
                }
            }
        }

        // per-signal grid barrier; fence by tid0 only (cumulative over __syncthreads)
        __syncthreads();
        if (tid == 0) {
            __threadfence();
            unsigned target = (unsigned)(t + 1);
            if (atomicAdd(&g_cnt[s], 1u) == NBS - 1) {
                g_cnt[s] = 0;
                __threadfence();
                g_sns[s] = target;
            } else {
                while (g_sns[s] != target) { }
                __threadfence();
            }
        }
        __syncthreads();
    }
}

extern "C" void kernel_launch(void* const* d_in, const int* in_sizes, int n_in,
                              void* d_out, int out_size) {
    const float* sig       = (const float*)d_in[0];  // (2,256,3)
    const float* Bext      = (const float*)d_in[1];  // (1,3,256,256)
    const float* Msat      = (const float*)d_in[2];  // scalar
    const int*   src_pos   = (const int*)d_in[3];    // (3,2)
    const int*   probe_pos = (const int*)d_in[4];    // (5,2)
    float*       out       = (float*)d_out;          // (2,256,5)

    mm_persist_kernel<<<NB, NTH>>>(sig, Bext, Msat, src_pos, probe_pos, out);
}